// round 2
// baseline (speedup 1.0000x reference)
#include <cuda_runtime.h>

// ---------------------------------------------------------------------------
// WTConv2d fused: 3-level Haar DWT -> 3x3 conv (128->128) -> inverse DWT + bias
// Fixed shapes: x(8,32,224,224) f32, weight(128,128,3,3) f32, bias(32) f32
// ---------------------------------------------------------------------------

#define B 8
#define C 32
#define C4 128

// Scratch (device globals; no allocation allowed)
__device__ float g_sub0[8 * 128 * 112 * 112];  // level-0 subbands (B, C*4, 112,112)
__device__ float g_y0[8 * 128 * 112 * 112];    // level-0 conv out
__device__ float g_sub1[8 * 128 * 56 * 56];
__device__ float g_y1[8 * 128 * 56 * 56];
__device__ float g_sub2[8 * 128 * 28 * 28];
__device__ float g_y2[8 * 128 * 28 * 28];
__device__ float g_ll1[8 * 32 * 56 * 56];      // idwt(level2) result
__device__ float g_ll0[8 * 32 * 112 * 112];    // idwt(level1) result
__device__ float g_wT[128 * 9 * 128];          // weights transposed [ic][tap][oc]

// ---------------------------------------------------------------------------
// Weight transpose: (oc, ic, ky, kx) -> [ic][ky*3+kx][oc]  (coalesced oc reads)
// ---------------------------------------------------------------------------
__global__ void transpose_w_kernel(const float* __restrict__ w) {
    int idx = blockIdx.x * blockDim.x + threadIdx.x;
    if (idx >= 128 * 128 * 9) return;
    int oc = idx / (128 * 9);
    int r = idx % (128 * 9);
    int ic = r / 9;
    int tap = r % 9;
    g_wT[(ic * 9 + tap) * 128 + oc] = w[idx];
}

// ---------------------------------------------------------------------------
// Haar DWT: in (B, Ctot, H, W) with logical channel c at index c*cmult
//           out (B, C*4, H/2, W/2), band k at channel c*4+k
// ---------------------------------------------------------------------------
__global__ void dwt_kernel(const float* __restrict__ in, float* __restrict__ out,
                           int cmult, int Ctot, int H, int W) {
    int h = H >> 1, w = W >> 1;
    long idx = (long)blockIdx.x * blockDim.x + threadIdx.x;
    long total = (long)B * C * h * w;
    if (idx >= total) return;
    int j = idx % w;
    long t = idx / w;
    int i = t % h; t /= h;
    int c = t % C;
    int b = t / C;

    const float* p = in + (((long)b * Ctot + (long)c * cmult) * H + 2 * i) * W + 2 * j;
    float a = p[0], bb = p[1], cc = p[W], dd = p[W + 1];

    long plane = (long)h * w;
    float* o = out + (((long)b * C4 + c * 4) * h + i) * w + j;
    o[0]         = (a + bb + cc + dd) * 0.5f;
    o[plane]     = (a - bb + cc - dd) * 0.5f;
    o[2 * plane] = (a + bb - cc - dd) * 0.5f;
    o[3 * plane] = (a - bb - cc + dd) * 0.5f;
}

// ---------------------------------------------------------------------------
// Direct 3x3 conv, 128ch -> 128ch, pad 1, stride 1.
// Block: 32 output channels x 8 rows x 8 cols tile, 256 threads.
//   lane (t%32) = output channel within group, row (t/32) = output row.
// Input tile (64 ic x 10x10) staged in smem, two chunks of 64 ic.
// Weights read from g_wT: lanes hit consecutive oc -> coalesced, L1-resident.
// ---------------------------------------------------------------------------
__global__ void __launch_bounds__(256) conv3x3_kernel(
    const float* __restrict__ in, float* __restrict__ out, int H, int W) {
    __shared__ float s_in[64 * 100];  // 25.6 KB

    int tx = threadIdx.x;
    int x0 = blockIdx.x * 8;
    int y0 = blockIdx.y * 8;
    int bz = blockIdx.z;       // b*4 + ocg
    int b = bz >> 2;
    int ocg = bz & 3;
    int lane = tx & 31;
    int row = tx >> 5;         // 0..7
    int oc = ocg * 32 + lane;

    float acc[8];
#pragma unroll
    for (int i = 0; i < 8; i++) acc[i] = 0.f;

    const float* inb = in + (long)b * 128 * H * W;

    for (int icc = 0; icc < 2; icc++) {
        __syncthreads();
        // cooperative load: 64 channels x 10x10 tile (zero-padded)
        for (int k = tx; k < 6400; k += 256) {
            int ic = k / 100;
            int r = k % 100;
            int yy = r / 10, xx = r % 10;
            int gy = y0 - 1 + yy, gx = x0 - 1 + xx;
            float v = 0.f;
            if (gy >= 0 && gy < H && gx >= 0 && gx < W)
                v = inb[((long)(icc * 64 + ic) * H + gy) * W + gx];
            s_in[k] = v;
        }
        __syncthreads();

        const float* wbase = g_wT + (long)(icc * 64) * 9 * 128 + oc;
#pragma unroll 1
        for (int ic = 0; ic < 64; ic++) {
            const float* srow = s_in + ic * 100 + row * 10;
            const float* wic = wbase + (long)ic * 9 * 128;
#pragma unroll
            for (int ky = 0; ky < 3; ky++) {
                float rr[10];
#pragma unroll
                for (int xx = 0; xx < 10; xx++) rr[xx] = srow[ky * 10 + xx];
#pragma unroll
                for (int kx = 0; kx < 3; kx++) {
                    float wv = __ldg(wic + (ky * 3 + kx) * 128);
#pragma unroll
                    for (int x = 0; x < 8; x++)
                        acc[x] = fmaf(wv, rr[x + kx], acc[x]);
                }
            }
        }
    }

    int oy = y0 + row;
    if (oy < H) {
        float* op = out + (((long)b * 128 + oc) * H + oy) * W + x0;
#pragma unroll
        for (int x = 0; x < 8; x++)
            if (x0 + x < W) op[x] = acc[x];
    }
}

// ---------------------------------------------------------------------------
// Inverse Haar DWT: y (B, C*4, h, w) band k at channel c*4+k.
// ll_add optional (B,C,h,w) added to the LL band before inverse.
// out (B, C, 2h, 2w) [+ bias if non-null].   s = 0.5
// ---------------------------------------------------------------------------
__global__ void idwt_kernel(const float* __restrict__ y, const float* __restrict__ ll_add,
                            float* __restrict__ out, const float* __restrict__ bias,
                            int h, int w) {
    long idx = (long)blockIdx.x * blockDim.x + threadIdx.x;
    long total = (long)B * C * h * w;
    if (idx >= total) return;
    int j = idx % w;
    long t = idx / w;
    int i = t % h; t /= h;
    int c = t % C;
    int b = t / C;

    long plane = (long)h * w;
    const float* p = y + (((long)b * C4 + c * 4) * h + i) * w + j;
    float ll = p[0];
    if (ll_add) ll += ll_add[(((long)b * C + c) * h + i) * w + j];
    float lh = p[plane], hl = p[2 * plane], hh = p[3 * plane];

    const float s = 0.5f;
    float a  = (ll + lh + hl + hh) * s;
    float bb = (ll - lh + hl - hh) * s;
    float cc = (ll + lh - hl - hh) * s;
    float dd = (ll - lh - hl + hh) * s;

    float bv = bias ? bias[c] : 0.f;
    int W2 = 2 * w;
    float* o = out + (((long)b * C + c) * (2 * h) + 2 * i) * W2 + 2 * j;
    o[0] = a + bv;
    o[1] = bb + bv;
    o[W2] = cc + bv;
    o[W2 + 1] = dd + bv;
}

// ---------------------------------------------------------------------------
extern "C" void kernel_launch(void* const* d_in, const int* in_sizes, int n_in,
                              void* d_out, int out_size) {
    const float* x = (const float*)d_in[0];
    const float* weight = (const float*)d_in[1];
    const float* bias = (const float*)d_in[2];
    float* out = (float*)d_out;

    float *sub0, *y0, *sub1, *y1, *sub2, *y2, *ll1, *ll0;
    cudaGetSymbolAddress((void**)&sub0, g_sub0);
    cudaGetSymbolAddress((void**)&y0, g_y0);
    cudaGetSymbolAddress((void**)&sub1, g_sub1);
    cudaGetSymbolAddress((void**)&y1, g_y1);
    cudaGetSymbolAddress((void**)&sub2, g_sub2);
    cudaGetSymbolAddress((void**)&y2, g_y2);
    cudaGetSymbolAddress((void**)&ll1, g_ll1);
    cudaGetSymbolAddress((void**)&ll0, g_ll0);

    // 0) transpose weights
    transpose_w_kernel<<<(128 * 128 * 9 + 255) / 256, 256>>>(weight);

    // 1) forward: dwt -> conv, 3 levels
    {
        long tot = (long)B * C * 112 * 112;
        dwt_kernel<<<(unsigned)((tot + 255) / 256), 256>>>(x, sub0, 1, 32, 224, 224);
        conv3x3_kernel<<<dim3(14, 14, B * 4), 256>>>(sub0, y0, 112, 112);
    }
    {
        long tot = (long)B * C * 56 * 56;
        dwt_kernel<<<(unsigned)((tot + 255) / 256), 256>>>(sub0, sub1, 4, 128, 112, 112);
        conv3x3_kernel<<<dim3(7, 7, B * 4), 256>>>(sub1, y1, 56, 56);
    }
    {
        long tot = (long)B * C * 28 * 28;
        dwt_kernel<<<(unsigned)((tot + 255) / 256), 256>>>(sub1, sub2, 4, 128, 56, 56);
        conv3x3_kernel<<<dim3(4, 4, B * 4), 256>>>(sub2, y2, 28, 28);
    }

    // 2) inverse cascade
    {
        long tot = (long)B * C * 28 * 28;
        idwt_kernel<<<(unsigned)((tot + 255) / 256), 256>>>(y2, nullptr, ll1, nullptr, 28, 28);
    }
    {
        long tot = (long)B * C * 56 * 56;
        idwt_kernel<<<(unsigned)((tot + 255) / 256), 256>>>(y1, ll1, ll0, nullptr, 56, 56);
    }
    {
        long tot = (long)B * C * 112 * 112;
        idwt_kernel<<<(unsigned)((tot + 255) / 256), 256>>>(y0, ll0, out, bias, 112, 112);
    }
}